// round 12
// baseline (speedup 1.0000x reference)
#include <cuda_runtime.h>
#include <cstdint>

// Problem constants
#define Bn 4
#define Sn 4096
#define Hn 1024
#define Dn 128
#define MCH 64                    // mpart K-chunks
#define NCH 32                    // suffix chunks
#define SCALE 0.08838834764831845f

// ---------------------------------------------------------------------------
// Scratch (device globals)
// ---------------------------------------------------------------------------
__device__ float g_k[Bn * Sn * Dn];
__device__ float g_v[Bn * Sn * Dn];
__device__ float g_Mpart[Bn * MCH * Dn * Dn];   // 16.8 MB
__device__ float g_M[Bn * Dn * Dn];
__device__ float g_P[Bn * Hn * Dn];
__device__ float g_chunk[Bn * NCH * Dn];
__device__ float g_sfx[Bn * Sn * Dn];

// ---------------------------------------------------------------------------
// Kernel 1: fused K/V projection.  C[m, n0+n] = sum_h x[m,h] * W[n0+n, h]
// 64x64 tiles -> grid (256, 4) = 1024 CTAs (balanced: ~7 per SM).
// 256 threads, 4x4 per thread, BK = 32.
// blockIdx.y: bit1 -> {Wk->g_k | Wv->g_v}, bit0 -> n0 = 0|64.
// ---------------------------------------------------------------------------
__global__ __launch_bounds__(256) void proj_kv_kernel(
    const float* __restrict__ x, const float* __restrict__ Wk,
    const float* __restrict__ Wv) {
    const float* W = (blockIdx.y >> 1) ? Wv : Wk;
    float* C = (blockIdx.y >> 1) ? g_v : g_k;
    const int n0 = (blockIdx.y & 1) * 64;
    const int m0 = blockIdx.x * 64;

    __shared__ __align__(16) float As[32][68];   // [k][m]
    __shared__ __align__(16) float Bs[32][68];   // [k][n]

    const int t = threadIdx.x;
    const int ty = t >> 4, tx = t & 15;

    float acc[4][4];
#pragma unroll
    for (int i = 0; i < 4; i++)
#pragma unroll
        for (int j = 0; j < 4; j++) acc[i][j] = 0.f;

    for (int k0 = 0; k0 < Hn; k0 += 32) {
        // A: 64 rows x 32 k -> transposed As[k][m]; 512 float4s, 2/thread
#pragma unroll
        for (int i = 0; i < 2; i++) {
            const int f = t + i * 256;
            const int row = f >> 3, kq = f & 7;
            const float4 va = *reinterpret_cast<const float4*>(
                x + (size_t)(m0 + row) * Hn + k0 + kq * 4);
            As[kq * 4 + 0][row] = va.x;
            As[kq * 4 + 1][row] = va.y;
            As[kq * 4 + 2][row] = va.z;
            As[kq * 4 + 3][row] = va.w;
        }
        // B: W rows n0..n0+63 x 32 k -> Bs[k][n]
#pragma unroll
        for (int i = 0; i < 2; i++) {
            const int f = t + i * 256;
            const int row = f >> 3, kq = f & 7;
            const float4 vb = *reinterpret_cast<const float4*>(
                W + (size_t)(n0 + row) * Hn + k0 + kq * 4);
            Bs[kq * 4 + 0][row] = vb.x;
            Bs[kq * 4 + 1][row] = vb.y;
            Bs[kq * 4 + 2][row] = vb.z;
            Bs[kq * 4 + 3][row] = vb.w;
        }
        __syncthreads();
#pragma unroll
        for (int kk = 0; kk < 32; kk++) {
            const float4 a = *reinterpret_cast<const float4*>(&As[kk][ty * 4]);
            const float4 b = *reinterpret_cast<const float4*>(&Bs[kk][tx * 4]);
            const float ra[4] = {a.x, a.y, a.z, a.w};
            const float rb[4] = {b.x, b.y, b.z, b.w};
#pragma unroll
            for (int i = 0; i < 4; i++)
#pragma unroll
                for (int j = 0; j < 4; j++) acc[i][j] += ra[i] * rb[j];
        }
        __syncthreads();
    }
#pragma unroll
    for (int i = 0; i < 4; i++) {
        float* dst = C + (size_t)(m0 + ty * 4 + i) * Dn + n0 + tx * 4;
        *reinterpret_cast<float4*>(dst) =
            make_float4(acc[i][0], acc[i][1], acc[i][2], acc[i][3]);
    }
}

// ---------------------------------------------------------------------------
// Kernel 2: split-K partials of M_b = kT_b @ v_b (kT = reshape of k)
// K-chunk 64 -> grid (64, Bn) = 256 CTAs. 8x8 per thread, BK=16.
// ---------------------------------------------------------------------------
__global__ __launch_bounds__(256) void mpart_kernel() {
    const int kc = blockIdx.x;    // 0..63
    const int b = blockIdx.y;
    const float* Ak = g_k + (size_t)b * Sn * Dn;  // viewed [128][4096]
    const float* V = g_v + (size_t)b * Sn * Dn;
    float* C = g_Mpart + ((size_t)(b * MCH + kc)) * Dn * Dn;

    __shared__ __align__(16) float As[16][132];
    __shared__ __align__(16) float Bs[16][132];
    const int t = threadIdx.x;
    const int ty = t >> 4, tx = t & 15;
    const int kbase = kc * 64;

    float acc[8][8];
#pragma unroll
    for (int i = 0; i < 8; i++)
#pragma unroll
        for (int j = 0; j < 8; j++) acc[i][j] = 0.f;

    for (int k0 = 0; k0 < 64; k0 += 16) {
#pragma unroll
        for (int i = 0; i < 2; i++) {
            int idx = t + i * 256;
            int row = idx >> 2, kq = idx & 3;
            const float4 va = *reinterpret_cast<const float4*>(
                Ak + (size_t)row * Sn + kbase + k0 + kq * 4);
            As[kq * 4 + 0][row] = va.x;
            As[kq * 4 + 1][row] = va.y;
            As[kq * 4 + 2][row] = va.z;
            As[kq * 4 + 3][row] = va.w;
        }
#pragma unroll
        for (int i = 0; i < 2; i++) {
            int idx = t + i * 256;
            int row = idx >> 5, cq = idx & 31;
            *reinterpret_cast<float4*>(&Bs[row][cq * 4]) =
                *reinterpret_cast<const float4*>(V + (size_t)(kbase + k0 + row) * Dn + cq * 4);
        }
        __syncthreads();
#pragma unroll
        for (int kk = 0; kk < 16; kk++) {
            const float4 a0 = *reinterpret_cast<const float4*>(&As[kk][ty * 8]);
            const float4 a1 = *reinterpret_cast<const float4*>(&As[kk][ty * 8 + 4]);
            const float4 b0 = *reinterpret_cast<const float4*>(&Bs[kk][tx * 8]);
            const float4 b1 = *reinterpret_cast<const float4*>(&Bs[kk][tx * 8 + 4]);
            const float ra[8] = {a0.x, a0.y, a0.z, a0.w, a1.x, a1.y, a1.z, a1.w};
            const float rb[8] = {b0.x, b0.y, b0.z, b0.w, b1.x, b1.y, b1.z, b1.w};
#pragma unroll
            for (int i = 0; i < 8; i++)
#pragma unroll
                for (int j = 0; j < 8; j++) acc[i][j] += ra[i] * rb[j];
        }
        __syncthreads();
    }
#pragma unroll
    for (int i = 0; i < 8; i++)
#pragma unroll
        for (int j = 0; j < 8; j += 4) {
            float4 o = make_float4(acc[i][j], acc[i][j + 1], acc[i][j + 2], acc[i][j + 3]);
            *reinterpret_cast<float4*>(C + (size_t)(ty * 8 + i) * Dn + tx * 8 + j) = o;
        }
}

// ---------------------------------------------------------------------------
// Kernel 3: reduce split-K partials -> g_M
// ---------------------------------------------------------------------------
__global__ void reduceM_kernel() {
    int idx = blockIdx.x * blockDim.x + threadIdx.x;
    int b = idx >> 14;
    int r = idx & 16383;
    float s = 0.f;
#pragma unroll
    for (int p = 0; p < MCH; p++) s += g_Mpart[((size_t)(b * MCH + p)) * Dn * Dn + r];
    g_M[idx] = s;
}

// ---------------------------------------------------------------------------
// Kernel 4: P_b = SCALE * Wq^T @ M_b, 32x128 tiles (R11 verbatim — passing)
// ---------------------------------------------------------------------------
__global__ __launch_bounds__(256) void gemmP_kernel(const float* __restrict__ Wq) {
    const int h0 = blockIdx.x * 32;
    const int b = blockIdx.y;
    const float* Mb = g_M + (size_t)b * Dn * Dn;
    float* P = g_P + (size_t)b * Hn * Dn;

    __shared__ __align__(16) float As[16][34];
    __shared__ __align__(16) float Bs[16][132];

    const int t = threadIdx.x;
    const int ty = t >> 4, tx = t & 15;

    float acc[2][8];
#pragma unroll
    for (int i = 0; i < 2; i++)
#pragma unroll
        for (int j = 0; j < 8; j++) acc[i][j] = 0.f;

    for (int k0 = 0; k0 < Dn; k0 += 16) {
        {
            const int d = t >> 4, h = (t & 15) * 2;
            const float2 wv = *reinterpret_cast<const float2*>(
                Wq + (size_t)(k0 + d) * Hn + h0 + h);
            As[d][h] = wv.x;
            As[d][h + 1] = wv.y;
        }
#pragma unroll
        for (int i = 0; i < 2; i++) {
            int idx = t + i * 256;
            int row = idx >> 5, cq = idx & 31;
            *reinterpret_cast<float4*>(&Bs[row][cq * 4]) =
                *reinterpret_cast<const float4*>(Mb + (size_t)(k0 + row) * Dn + cq * 4);
        }
        __syncthreads();
#pragma unroll
        for (int kk = 0; kk < 16; kk++) {
            const float ra0 = As[kk][ty];
            const float ra1 = As[kk][ty + 16];
            const float4 b0 = *reinterpret_cast<const float4*>(&Bs[kk][tx * 8]);
            const float4 b1 = *reinterpret_cast<const float4*>(&Bs[kk][tx * 8 + 4]);
            const float rb[8] = {b0.x, b0.y, b0.z, b0.w, b1.x, b1.y, b1.z, b1.w};
#pragma unroll
            for (int j = 0; j < 8; j++) acc[0][j] += ra0 * rb[j];
#pragma unroll
            for (int j = 0; j < 8; j++) acc[1][j] += ra1 * rb[j];
        }
        __syncthreads();
    }
#pragma unroll
    for (int i = 0; i < 2; i++) {
        float* dst = P + (size_t)(h0 + ty + i * 16) * Dn + tx * 8;
        *reinterpret_cast<float4*>(dst) =
            make_float4(acc[i][0] * SCALE, acc[i][1] * SCALE, acc[i][2] * SCALE,
                        acc[i][3] * SCALE);
        *reinterpret_cast<float4*>(dst + 4) =
            make_float4(acc[i][4] * SCALE, acc[i][5] * SCALE, acc[i][6] * SCALE,
                        acc[i][7] * SCALE);
    }
}

// ---------------------------------------------------------------------------
// Kernel 5a/5b: suffix machinery (passing, unchanged)
// ---------------------------------------------------------------------------
__global__ void chunksum_kernel() {
    const int c = blockIdx.x, b = blockIdx.y, e = threadIdx.x;
    const float* V = g_v + ((size_t)b * Sn + c * 128) * Dn;
    float s = 0.f;
#pragma unroll 8
    for (int i = 0; i < 128; i++) s += V[(size_t)i * Dn + e];
    g_chunk[((size_t)b * NCH + c) * Dn + e] = s;
}

__global__ void suffix_kernel() {
    const int c = blockIdx.x, b = blockIdx.y, e = threadIdx.x;
    float tail = 0.f;
    for (int cc = c + 1; cc < NCH; cc++) tail += g_chunk[((size_t)b * NCH + cc) * Dn + e];
    const float* V = g_v + ((size_t)b * Sn + c * 128) * Dn;
    float* Sx = g_sfx + ((size_t)b * Sn + c * 128) * Dn;
    for (int i = 127; i >= 0; i--) {
        Sx[(size_t)i * Dn + e] = tail;
        tail += V[(size_t)i * Dn + e];
    }
}

// ---------------------------------------------------------------------------
// Kernel 6: res = x @ P_b - 1e9 * sfx
// 16x128 tiles -> 1024 CTAs (balanced). 128 threads, 2x8 per thread, BK=32.
// ---------------------------------------------------------------------------
__global__ __launch_bounds__(128) void final_kernel(const float* __restrict__ x,
                                                    float* __restrict__ out) {
    const int m0 = blockIdx.x * 16;
    const int b = m0 / Sn;
    const float* P = g_P + (size_t)b * Hn * Dn;

    __shared__ __align__(16) float As[32][20];    // [k][m] (16 + pad)
    __shared__ __align__(16) float Bs[32][132];   // [k][e]

    const int t = threadIdx.x;
    const int ty = t >> 4, tx = t & 15;   // 8 x 16

    float acc[2][8];
#pragma unroll
    for (int i = 0; i < 2; i++)
#pragma unroll
        for (int j = 0; j < 8; j++) acc[i][j] = 0.f;

    for (int k0 = 0; k0 < Hn; k0 += 32) {
        {   // A: 16 rows x 32 k = 128 float4s, 1/thread, transposed
            const int row = t >> 3, kq = t & 7;
            const float4 va = *reinterpret_cast<const float4*>(
                x + (size_t)(m0 + row) * Hn + k0 + kq * 4);
            As[kq * 4 + 0][row] = va.x;
            As[kq * 4 + 1][row] = va.y;
            As[kq * 4 + 2][row] = va.z;
            As[kq * 4 + 3][row] = va.w;
        }
        // B: P rows k0..k0+31 x 128 e = 1024 float4s, 8/thread
#pragma unroll
        for (int i = 0; i < 8; i++) {
            const int idx = t + i * 128;
            const int row = idx >> 5, cq = idx & 31;
            *reinterpret_cast<float4*>(&Bs[row][cq * 4]) =
                *reinterpret_cast<const float4*>(P + (size_t)(k0 + row) * Dn + cq * 4);
        }
        __syncthreads();
#pragma unroll
        for (int kk = 0; kk < 32; kk++) {
            const float a0 = As[kk][ty * 2];
            const float a1 = As[kk][ty * 2 + 1];
            const float4 b0 = *reinterpret_cast<const float4*>(&Bs[kk][tx * 8]);
            const float4 b1 = *reinterpret_cast<const float4*>(&Bs[kk][tx * 8 + 4]);
            const float rb[8] = {b0.x, b0.y, b0.z, b0.w, b1.x, b1.y, b1.z, b1.w};
#pragma unroll
            for (int j = 0; j < 8; j++) acc[0][j] += a0 * rb[j];
#pragma unroll
            for (int j = 0; j < 8; j++) acc[1][j] += a1 * rb[j];
        }
        __syncthreads();
    }

#pragma unroll
    for (int i = 0; i < 2; i++) {
        const int m = m0 + ty * 2 + i;
        const float* sp = g_sfx + (size_t)m * Dn + tx * 8;
        const float4 s0 = *reinterpret_cast<const float4*>(sp);
        const float4 s1 = *reinterpret_cast<const float4*>(sp + 4);
        float* dst = out + (size_t)m * Dn + tx * 8;
        *reinterpret_cast<float4*>(dst) =
            make_float4(acc[i][0] - 1.0e9f * s0.x, acc[i][1] - 1.0e9f * s0.y,
                        acc[i][2] - 1.0e9f * s0.z, acc[i][3] - 1.0e9f * s0.w);
        *reinterpret_cast<float4*>(dst + 4) =
            make_float4(acc[i][4] - 1.0e9f * s1.x, acc[i][5] - 1.0e9f * s1.y,
                        acc[i][6] - 1.0e9f * s1.z, acc[i][7] - 1.0e9f * s1.w);
    }
}

// ---------------------------------------------------------------------------
// launch
// ---------------------------------------------------------------------------
extern "C" void kernel_launch(void* const* d_in, const int* in_sizes, int n_in,
                              void* d_out, int out_size) {
    const float* x = (const float*)d_in[0];
    const float* Wq = (const float*)d_in[1];
    const float* Wk = (const float*)d_in[2];
    const float* Wv = (const float*)d_in[3];
    float* out = (float*)d_out;

    proj_kv_kernel<<<dim3(Bn * Sn / 64, 4), 256>>>(x, Wk, Wv);
    mpart_kernel<<<dim3(MCH, Bn), 256>>>();
    reduceM_kernel<<<256, 256>>>();
    gemmP_kernel<<<dim3(Hn / 32, Bn), 256>>>(Wq);
    chunksum_kernel<<<dim3(NCH, Bn), 128>>>();
    suffix_kernel<<<dim3(NCH, Bn), 128>>>();
    final_kernel<<<Bn * Sn / 16, 128>>>(x, out);
}

// round 14
// speedup vs baseline: 1.4446x; 1.4446x over previous
#include <cuda_runtime.h>
#include <cstdint>

// Problem constants
#define Bn 4
#define Sn 4096
#define Hn 1024
#define Dn 128
#define NCH 32
#define SCALE 0.08838834764831845f

// ---------------------------------------------------------------------------
// Scratch (device globals)
// ---------------------------------------------------------------------------
__device__ float g_k[Bn * Sn * Dn];
__device__ float g_v[Bn * Sn * Dn];
__device__ float g_Mpart[Bn * NCH * Dn * Dn];
__device__ float g_M[Bn * Dn * Dn];
__device__ float g_P[Bn * Hn * Dn];
__device__ float g_chunk[Bn * NCH * Dn];
__device__ float g_sfx[Bn * Sn * Dn];

// ---------------------------------------------------------------------------
// Packed fp32x2 helpers (used by mpart — R11-proven)
// ---------------------------------------------------------------------------
#define FFMA2(d, a, b) \
    asm("fma.rn.f32x2 %0, %1, %2, %0;" : "+l"(d) : "l"(a), "l"(b))
#define DUP2(d, f) \
    asm("mov.b64 %0, {%1, %1};" : "=l"(d) : "f"(f))
#define UNPK(lo, hi, q) \
    asm("mov.b64 {%0, %1}, %2;" : "=f"(lo), "=f"(hi) : "l"(q))

#define DECL_Q                                                                  \
    unsigned long long q00 = 0, q01 = 0, q02 = 0, q03 = 0;                      \
    unsigned long long q10 = 0, q11 = 0, q12 = 0, q13 = 0;                      \
    unsigned long long q20 = 0, q21 = 0, q22 = 0, q23 = 0;                      \
    unsigned long long q30 = 0, q31 = 0, q32 = 0, q33 = 0;                      \
    unsigned long long q40 = 0, q41 = 0, q42 = 0, q43 = 0;                      \
    unsigned long long q50 = 0, q51 = 0, q52 = 0, q53 = 0;                      \
    unsigned long long q60 = 0, q61 = 0, q62 = 0, q63 = 0;                      \
    unsigned long long q70 = 0, q71 = 0, q72 = 0, q73 = 0;

#define ROWQ(I, F)                                                              \
    do {                                                                        \
        unsigned long long d_;                                                  \
        DUP2(d_, F);                                                            \
        FFMA2(q##I##0, d_, rb0);                                                \
        FFMA2(q##I##1, d_, rb1);                                                \
        FFMA2(q##I##2, d_, rb2);                                                \
        FFMA2(q##I##3, d_, rb3);                                                \
    } while (0)

#define KSTEP8x8                                                                \
    ROWQ(0, a0.x); ROWQ(1, a0.y); ROWQ(2, a0.z); ROWQ(3, a0.w);                 \
    ROWQ(4, a1.x); ROWQ(5, a1.y); ROWQ(6, a1.z); ROWQ(7, a1.w);

#define UNPACK_ROW(I)                                                           \
    float c0, c1, c2, c3, c4, c5, c6, c7;                                       \
    UNPK(c0, c1, q##I##0);                                                      \
    UNPK(c2, c3, q##I##1);                                                      \
    UNPK(c4, c5, q##I##2);                                                      \
    UNPK(c6, c7, q##I##3);

// ---------------------------------------------------------------------------
// Kernel 1: fused K/V projection.  C[m,n] = sum_h x[m,h] * W[n,h]
// 64x128 tile, 128 threads, 8x8 per thread (intensity preserved), BK=16.
// grid (256, 2) = 512 CTAs -> ~4 resident/SM, fine-grain wave packing.
// ---------------------------------------------------------------------------
__global__ __launch_bounds__(128) void proj_kv_kernel(
    const float* __restrict__ x, const float* __restrict__ Wk,
    const float* __restrict__ Wv) {
    const float* W = blockIdx.y ? Wv : Wk;
    float* C = blockIdx.y ? g_v : g_k;
    const int m0 = blockIdx.x * 64;

    __shared__ __align__(16) float As[16][68];    // [k][m] 64 + pad
    __shared__ __align__(16) float Bs[16][132];   // [k][n] 128 + pad

    const int t = threadIdx.x;
    const int ty = t >> 4, tx = t & 15;   // 8 x 16 -> 8x8 thread tile

    float acc[8][8];
#pragma unroll
    for (int i = 0; i < 8; i++)
#pragma unroll
        for (int j = 0; j < 8; j++) acc[i][j] = 0.f;

    for (int k0 = 0; k0 < Hn; k0 += 16) {
        // A: 64 rows x 16 k = 256 float4s, 2/thread, transposed
#pragma unroll
        for (int i = 0; i < 2; i++) {
            const int f = t + i * 128;
            const int row = f >> 2, kq = f & 3;
            const float4 va = *reinterpret_cast<const float4*>(
                x + (size_t)(m0 + row) * Hn + k0 + kq * 4);
            As[kq * 4 + 0][row] = va.x;
            As[kq * 4 + 1][row] = va.y;
            As[kq * 4 + 2][row] = va.z;
            As[kq * 4 + 3][row] = va.w;
        }
        // B: 128 W rows x 16 k = 512 float4s, 4/thread, transposed
#pragma unroll
        for (int i = 0; i < 4; i++) {
            const int f = t + i * 128;
            const int row = f >> 2, kq = f & 3;
            const float4 vb = *reinterpret_cast<const float4*>(
                W + (size_t)row * Hn + k0 + kq * 4);
            Bs[kq * 4 + 0][row] = vb.x;
            Bs[kq * 4 + 1][row] = vb.y;
            Bs[kq * 4 + 2][row] = vb.z;
            Bs[kq * 4 + 3][row] = vb.w;
        }
        __syncthreads();
#pragma unroll
        for (int kk = 0; kk < 16; kk++) {
            const float4 a0 = *reinterpret_cast<const float4*>(&As[kk][ty * 8]);
            const float4 a1 = *reinterpret_cast<const float4*>(&As[kk][ty * 8 + 4]);
            const float4 b0 = *reinterpret_cast<const float4*>(&Bs[kk][tx * 8]);
            const float4 b1 = *reinterpret_cast<const float4*>(&Bs[kk][tx * 8 + 4]);
            const float ra[8] = {a0.x, a0.y, a0.z, a0.w, a1.x, a1.y, a1.z, a1.w};
            const float rb[8] = {b0.x, b0.y, b0.z, b0.w, b1.x, b1.y, b1.z, b1.w};
#pragma unroll
            for (int i = 0; i < 8; i++)
#pragma unroll
                for (int j = 0; j < 8; j++) acc[i][j] += ra[i] * rb[j];
        }
        __syncthreads();
    }
#pragma unroll
    for (int i = 0; i < 8; i++) {
        float* dst = C + (size_t)(m0 + ty * 8 + i) * Dn + tx * 8;
        *reinterpret_cast<float4*>(dst) =
            make_float4(acc[i][0], acc[i][1], acc[i][2], acc[i][3]);
        *reinterpret_cast<float4*>(dst + 4) =
            make_float4(acc[i][4], acc[i][5], acc[i][6], acc[i][7]);
    }
}

// ---------------------------------------------------------------------------
// Kernel 2: split-K partials of M_b = kT_b @ v_b (R11 verbatim — passing)
// ---------------------------------------------------------------------------
__global__ __launch_bounds__(256) void mpart_kernel() {
    const int kc = blockIdx.x;
    const int b = blockIdx.y;
    const float* Ak = g_k + (size_t)b * Sn * Dn;  // viewed [128][4096]
    const float* V = g_v + (size_t)b * Sn * Dn;
    float* C = g_Mpart + ((size_t)(b * NCH + kc)) * Dn * Dn;

    __shared__ __align__(16) float As[16][132];
    __shared__ __align__(16) float Bs[16][132];
    const int t = threadIdx.x;
    const int ty = t >> 4, tx = t & 15;
    const int kbase = kc * 128;

    DECL_Q

    for (int k0 = 0; k0 < 128; k0 += 16) {
#pragma unroll
        for (int i = 0; i < 2; i++) {
            int idx = t + i * 256;
            int row = idx >> 2, kq = idx & 3;
            const float4 va = *reinterpret_cast<const float4*>(
                Ak + (size_t)row * Sn + kbase + k0 + kq * 4);
            As[kq * 4 + 0][row] = va.x;
            As[kq * 4 + 1][row] = va.y;
            As[kq * 4 + 2][row] = va.z;
            As[kq * 4 + 3][row] = va.w;
        }
#pragma unroll
        for (int i = 0; i < 2; i++) {
            int idx = t + i * 256;
            int row = idx >> 5, cq = idx & 31;
            *reinterpret_cast<float4*>(&Bs[row][cq * 4]) =
                *reinterpret_cast<const float4*>(V + (size_t)(kbase + k0 + row) * Dn + cq * 4);
        }
        __syncthreads();
#pragma unroll
        for (int kk = 0; kk < 16; kk++) {
            const float4 a0 = *reinterpret_cast<const float4*>(&As[kk][ty * 8]);
            const float4 a1 = *reinterpret_cast<const float4*>(&As[kk][ty * 8 + 4]);
            const unsigned long long rb0 =
                *reinterpret_cast<const unsigned long long*>(&Bs[kk][tx * 8 + 0]);
            const unsigned long long rb1 =
                *reinterpret_cast<const unsigned long long*>(&Bs[kk][tx * 8 + 2]);
            const unsigned long long rb2 =
                *reinterpret_cast<const unsigned long long*>(&Bs[kk][tx * 8 + 4]);
            const unsigned long long rb3 =
                *reinterpret_cast<const unsigned long long*>(&Bs[kk][tx * 8 + 6]);
            KSTEP8x8
        }
        __syncthreads();
    }

#define MP_STORE(I, i)                                                          \
    do {                                                                        \
        UNPACK_ROW(I)                                                           \
        float* dst = C + (size_t)(ty * 8 + (i)) * Dn + tx * 8;                  \
        *reinterpret_cast<float4*>(dst) = make_float4(c0, c1, c2, c3);          \
        *reinterpret_cast<float4*>(dst + 4) = make_float4(c4, c5, c6, c7);      \
    } while (0)
    MP_STORE(0, 0); MP_STORE(1, 1); MP_STORE(2, 2); MP_STORE(3, 3);
    MP_STORE(4, 4); MP_STORE(5, 5); MP_STORE(6, 6); MP_STORE(7, 7);
#undef MP_STORE
}

// ---------------------------------------------------------------------------
// Kernel 3: reduce split-K partials -> g_M
// ---------------------------------------------------------------------------
__global__ void reduceM_kernel() {
    int idx = blockIdx.x * blockDim.x + threadIdx.x;
    int b = idx >> 14;
    int r = idx & 16383;
    float s = 0.f;
#pragma unroll
    for (int p = 0; p < NCH; p++) s += g_Mpart[((size_t)(b * NCH + p)) * Dn * Dn + r];
    g_M[idx] = s;
}

// ---------------------------------------------------------------------------
// Kernel 4: P_b = SCALE * Wq^T @ M_b, 32x128 tiles (R11 verbatim — passing)
// ---------------------------------------------------------------------------
__global__ __launch_bounds__(256) void gemmP_kernel(const float* __restrict__ Wq) {
    const int h0 = blockIdx.x * 32;
    const int b = blockIdx.y;
    const float* Mb = g_M + (size_t)b * Dn * Dn;
    float* P = g_P + (size_t)b * Hn * Dn;

    __shared__ __align__(16) float As[16][34];
    __shared__ __align__(16) float Bs[16][132];

    const int t = threadIdx.x;
    const int ty = t >> 4, tx = t & 15;

    float acc[2][8];
#pragma unroll
    for (int i = 0; i < 2; i++)
#pragma unroll
        for (int j = 0; j < 8; j++) acc[i][j] = 0.f;

    for (int k0 = 0; k0 < Dn; k0 += 16) {
        {
            const int d = t >> 4, h = (t & 15) * 2;
            const float2 wv = *reinterpret_cast<const float2*>(
                Wq + (size_t)(k0 + d) * Hn + h0 + h);
            As[d][h] = wv.x;
            As[d][h + 1] = wv.y;
        }
#pragma unroll
        for (int i = 0; i < 2; i++) {
            int idx = t + i * 256;
            int row = idx >> 5, cq = idx & 31;
            *reinterpret_cast<float4*>(&Bs[row][cq * 4]) =
                *reinterpret_cast<const float4*>(Mb + (size_t)(k0 + row) * Dn + cq * 4);
        }
        __syncthreads();
#pragma unroll
        for (int kk = 0; kk < 16; kk++) {
            const float ra0 = As[kk][ty];
            const float ra1 = As[kk][ty + 16];
            const float4 b0 = *reinterpret_cast<const float4*>(&Bs[kk][tx * 8]);
            const float4 b1 = *reinterpret_cast<const float4*>(&Bs[kk][tx * 8 + 4]);
            const float rb[8] = {b0.x, b0.y, b0.z, b0.w, b1.x, b1.y, b1.z, b1.w};
#pragma unroll
            for (int j = 0; j < 8; j++) acc[0][j] += ra0 * rb[j];
#pragma unroll
            for (int j = 0; j < 8; j++) acc[1][j] += ra1 * rb[j];
        }
        __syncthreads();
    }
#pragma unroll
    for (int i = 0; i < 2; i++) {
        float* dst = P + (size_t)(h0 + ty + i * 16) * Dn + tx * 8;
        *reinterpret_cast<float4*>(dst) =
            make_float4(acc[i][0] * SCALE, acc[i][1] * SCALE, acc[i][2] * SCALE,
                        acc[i][3] * SCALE);
        *reinterpret_cast<float4*>(dst + 4) =
            make_float4(acc[i][4] * SCALE, acc[i][5] * SCALE, acc[i][6] * SCALE,
                        acc[i][7] * SCALE);
    }
}

// ---------------------------------------------------------------------------
// Kernel 5a/5b: suffix machinery (R11 verbatim — passing)
// ---------------------------------------------------------------------------
__global__ void chunksum_kernel() {
    const int c = blockIdx.x, b = blockIdx.y, e = threadIdx.x;
    const float* V = g_v + ((size_t)b * Sn + c * 128) * Dn;
    float s = 0.f;
#pragma unroll 8
    for (int i = 0; i < 128; i++) s += V[(size_t)i * Dn + e];
    g_chunk[((size_t)b * NCH + c) * Dn + e] = s;
}

__global__ void suffix_kernel() {
    const int c = blockIdx.x, b = blockIdx.y, e = threadIdx.x;
    float tail = 0.f;
    for (int cc = c + 1; cc < NCH; cc++) tail += g_chunk[((size_t)b * NCH + cc) * Dn + e];
    const float* V = g_v + ((size_t)b * Sn + c * 128) * Dn;
    float* Sx = g_sfx + ((size_t)b * Sn + c * 128) * Dn;
    for (int i = 127; i >= 0; i--) {
        Sx[(size_t)i * Dn + e] = tail;
        tail += V[(size_t)i * Dn + e];
    }
}

// ---------------------------------------------------------------------------
// Kernel 6: res = x @ P_b - 1e9 * sfx
// 64x128 tile, 128 threads, 8x8 per thread, BK=16 -> 256 CTAs.
// ---------------------------------------------------------------------------
__global__ __launch_bounds__(128) void final_kernel(const float* __restrict__ x,
                                                    float* __restrict__ out) {
    const int m0 = blockIdx.x * 64;
    const int b = m0 / Sn;
    const float* P = g_P + (size_t)b * Hn * Dn;

    __shared__ __align__(16) float As[16][68];    // [k][m]
    __shared__ __align__(16) float Bs[16][132];   // [k][e]

    const int t = threadIdx.x;
    const int ty = t >> 4, tx = t & 15;

    float acc[8][8];
#pragma unroll
    for (int i = 0; i < 8; i++)
#pragma unroll
        for (int j = 0; j < 8; j++) acc[i][j] = 0.f;

    for (int k0 = 0; k0 < Hn; k0 += 16) {
        // A: 64 rows x 16 k, 2 float4/thread, transposed
#pragma unroll
        for (int i = 0; i < 2; i++) {
            const int f = t + i * 128;
            const int row = f >> 2, kq = f & 3;
            const float4 va = *reinterpret_cast<const float4*>(
                x + (size_t)(m0 + row) * Hn + k0 + kq * 4);
            As[kq * 4 + 0][row] = va.x;
            As[kq * 4 + 1][row] = va.y;
            As[kq * 4 + 2][row] = va.z;
            As[kq * 4 + 3][row] = va.w;
        }
        // B: P rows k0..k0+15 x 128 e = 512 float4s, 4/thread, direct
#pragma unroll
        for (int i = 0; i < 4; i++) {
            const int idx = t + i * 128;
            const int row = idx >> 5, cq = idx & 31;
            *reinterpret_cast<float4*>(&Bs[row][cq * 4]) =
                *reinterpret_cast<const float4*>(P + (size_t)(k0 + row) * Dn + cq * 4);
        }
        __syncthreads();
#pragma unroll
        for (int kk = 0; kk < 16; kk++) {
            const float4 a0 = *reinterpret_cast<const float4*>(&As[kk][ty * 8]);
            const float4 a1 = *reinterpret_cast<const float4*>(&As[kk][ty * 8 + 4]);
            const float4 b0 = *reinterpret_cast<const float4*>(&Bs[kk][tx * 8]);
            const float4 b1 = *reinterpret_cast<const float4*>(&Bs[kk][tx * 8 + 4]);
            const float ra[8] = {a0.x, a0.y, a0.z, a0.w, a1.x, a1.y, a1.z, a1.w};
            const float rb[8] = {b0.x, b0.y, b0.z, b0.w, b1.x, b1.y, b1.z, b1.w};
#pragma unroll
            for (int i = 0; i < 8; i++)
#pragma unroll
                for (int j = 0; j < 8; j++) acc[i][j] += ra[i] * rb[j];
        }
        __syncthreads();
    }

#pragma unroll
    for (int i = 0; i < 8; i++) {
        const int m = m0 + ty * 8 + i;
        const float* sp = g_sfx + (size_t)m * Dn + tx * 8;
        const float4 s0 = *reinterpret_cast<const float4*>(sp);
        const float4 s1 = *reinterpret_cast<const float4*>(sp + 4);
        float* dst = out + (size_t)m * Dn + tx * 8;
        *reinterpret_cast<float4*>(dst) =
            make_float4(acc[i][0] - 1.0e9f * s0.x, acc[i][1] - 1.0e9f * s0.y,
                        acc[i][2] - 1.0e9f * s0.z, acc[i][3] - 1.0e9f * s0.w);
        *reinterpret_cast<float4*>(dst + 4) =
            make_float4(acc[i][4] - 1.0e9f * s1.x, acc[i][5] - 1.0e9f * s1.y,
                        acc[i][6] - 1.0e9f * s1.z, acc[i][7] - 1.0e9f * s1.w);
    }
}

// ---------------------------------------------------------------------------
// launch
// ---------------------------------------------------------------------------
extern "C" void kernel_launch(void* const* d_in, const int* in_sizes, int n_in,
                              void* d_out, int out_size) {
    const float* x = (const float*)d_in[0];
    const float* Wq = (const float*)d_in[1];
    const float* Wk = (const float*)d_in[2];
    const float* Wv = (const float*)d_in[3];
    float* out = (float*)d_out;

    proj_kv_kernel<<<dim3(Bn * Sn / 64, 2), 128>>>(x, Wk, Wv);
    mpart_kernel<<<dim3(NCH, Bn), 256>>>();
    reduceM_kernel<<<256, 256>>>();
    gemmP_kernel<<<dim3(Hn / 32, Bn), 256>>>(Wq);
    chunksum_kernel<<<dim3(NCH, Bn), 128>>>();
    suffix_kernel<<<dim3(NCH, Bn), 128>>>();
    final_kernel<<<Bn * Sn / 64, 128>>>(x, out);
}

// round 15
// speedup vs baseline: 1.4737x; 1.0202x over previous
#include <cuda_runtime.h>
#include <cstdint>

// Problem constants
#define Bn 4
#define Sn 4096
#define Hn 1024
#define Dn 128
#define NCH 32
#define SCALE 0.08838834764831845f

// ---------------------------------------------------------------------------
// Scratch (device globals)
// ---------------------------------------------------------------------------
__device__ float g_k[Bn * Sn * Dn];
__device__ float g_v[Bn * Sn * Dn];
__device__ float g_Mpart[Bn * NCH * Dn * Dn];
__device__ float g_M[Bn * Dn * Dn];
__device__ float g_Ppart[2 * Bn * Hn * Dn];   // split-K partials of P
__device__ float g_P[Bn * Hn * Dn];
__device__ float g_chunk[Bn * NCH * Dn];
__device__ float g_sfx[Bn * Sn * Dn];

// ---------------------------------------------------------------------------
// Packed fp32x2 helpers (R10/R11-proven)
// ---------------------------------------------------------------------------
#define FFMA2(d, a, b) \
    asm("fma.rn.f32x2 %0, %1, %2, %0;" : "+l"(d) : "l"(a), "l"(b))
#define DUP2(d, f) \
    asm("mov.b64 %0, {%1, %1};" : "=l"(d) : "f"(f))
#define UNPK(lo, hi, q) \
    asm("mov.b64 {%0, %1}, %2;" : "=f"(lo), "=f"(hi) : "l"(q))

#define DECL_Q                                                                  \
    unsigned long long q00 = 0, q01 = 0, q02 = 0, q03 = 0;                      \
    unsigned long long q10 = 0, q11 = 0, q12 = 0, q13 = 0;                      \
    unsigned long long q20 = 0, q21 = 0, q22 = 0, q23 = 0;                      \
    unsigned long long q30 = 0, q31 = 0, q32 = 0, q33 = 0;                      \
    unsigned long long q40 = 0, q41 = 0, q42 = 0, q43 = 0;                      \
    unsigned long long q50 = 0, q51 = 0, q52 = 0, q53 = 0;                      \
    unsigned long long q60 = 0, q61 = 0, q62 = 0, q63 = 0;                      \
    unsigned long long q70 = 0, q71 = 0, q72 = 0, q73 = 0;

#define ROWQ(I, F)                                                              \
    do {                                                                        \
        unsigned long long d_;                                                  \
        DUP2(d_, F);                                                            \
        FFMA2(q##I##0, d_, rb0);                                                \
        FFMA2(q##I##1, d_, rb1);                                                \
        FFMA2(q##I##2, d_, rb2);                                                \
        FFMA2(q##I##3, d_, rb3);                                                \
    } while (0)

#define KSTEP8x8                                                                \
    ROWQ(0, a0.x); ROWQ(1, a0.y); ROWQ(2, a0.z); ROWQ(3, a0.w);                 \
    ROWQ(4, a1.x); ROWQ(5, a1.y); ROWQ(6, a1.z); ROWQ(7, a1.w);

#define UNPACK_ROW(I)                                                           \
    float c0, c1, c2, c3, c4, c5, c6, c7;                                       \
    UNPK(c0, c1, q##I##0);                                                      \
    UNPK(c2, c3, q##I##1);                                                      \
    UNPK(c4, c5, q##I##2);                                                      \
    UNPK(c6, c7, q##I##3);

// ---------------------------------------------------------------------------
// Kernel 1: fused K/V projection (R10/R11 verbatim — best measured)
// ---------------------------------------------------------------------------
__global__ __launch_bounds__(256) void proj_kv_kernel(
    const float* __restrict__ x, const float* __restrict__ Wk,
    const float* __restrict__ Wv) {
    const float* W = blockIdx.y ? Wv : Wk;
    float* C = blockIdx.y ? g_v : g_k;
    const int m0 = blockIdx.x * 128;

    __shared__ __align__(16) float As[16][132];
    __shared__ __align__(16) float Bs[16][132];

    const int t = threadIdx.x;
    const int ty = t >> 4, tx = t & 15;

    DECL_Q

    for (int k0 = 0; k0 < Hn; k0 += 16) {
#pragma unroll
        for (int i = 0; i < 2; i++) {
            int idx = t + i * 256;
            int row = idx >> 2, kq = idx & 3;
            const float4 va = *reinterpret_cast<const float4*>(
                x + (size_t)(m0 + row) * Hn + k0 + kq * 4);
            As[kq * 4 + 0][row] = va.x;
            As[kq * 4 + 1][row] = va.y;
            As[kq * 4 + 2][row] = va.z;
            As[kq * 4 + 3][row] = va.w;
        }
#pragma unroll
        for (int i = 0; i < 2; i++) {
            int idx = t + i * 256;
            int row = idx >> 2, kq = idx & 3;
            const float4 vb = *reinterpret_cast<const float4*>(
                W + (size_t)row * Hn + k0 + kq * 4);
            Bs[kq * 4 + 0][row] = vb.x;
            Bs[kq * 4 + 1][row] = vb.y;
            Bs[kq * 4 + 2][row] = vb.z;
            Bs[kq * 4 + 3][row] = vb.w;
        }
        __syncthreads();
#pragma unroll
        for (int kk = 0; kk < 16; kk++) {
            const float4 a0 = *reinterpret_cast<const float4*>(&As[kk][ty * 8]);
            const float4 a1 = *reinterpret_cast<const float4*>(&As[kk][ty * 8 + 4]);
            const unsigned long long rb0 =
                *reinterpret_cast<const unsigned long long*>(&Bs[kk][tx * 8 + 0]);
            const unsigned long long rb1 =
                *reinterpret_cast<const unsigned long long*>(&Bs[kk][tx * 8 + 2]);
            const unsigned long long rb2 =
                *reinterpret_cast<const unsigned long long*>(&Bs[kk][tx * 8 + 4]);
            const unsigned long long rb3 =
                *reinterpret_cast<const unsigned long long*>(&Bs[kk][tx * 8 + 6]);
            KSTEP8x8
        }
        __syncthreads();
    }

#define PROJ_STORE(I, i)                                                        \
    do {                                                                        \
        UNPACK_ROW(I)                                                           \
        float* dst = C + (size_t)(m0 + ty * 8 + (i)) * Dn + tx * 8;             \
        *reinterpret_cast<float4*>(dst) = make_float4(c0, c1, c2, c3);          \
        *reinterpret_cast<float4*>(dst + 4) = make_float4(c4, c5, c6, c7);      \
    } while (0)
    PROJ_STORE(0, 0); PROJ_STORE(1, 1); PROJ_STORE(2, 2); PROJ_STORE(3, 3);
    PROJ_STORE(4, 4); PROJ_STORE(5, 5); PROJ_STORE(6, 6); PROJ_STORE(7, 7);
#undef PROJ_STORE
}

// ---------------------------------------------------------------------------
// Kernel 2: split-K partials of M_b = kT_b @ v_b (R10/R11 verbatim)
// ---------------------------------------------------------------------------
__global__ __launch_bounds__(256) void mpart_kernel() {
    const int kc = blockIdx.x;
    const int b = blockIdx.y;
    const float* Ak = g_k + (size_t)b * Sn * Dn;  // viewed [128][4096]
    const float* V = g_v + (size_t)b * Sn * Dn;
    float* C = g_Mpart + ((size_t)(b * NCH + kc)) * Dn * Dn;

    __shared__ __align__(16) float As[16][132];
    __shared__ __align__(16) float Bs[16][132];
    const int t = threadIdx.x;
    const int ty = t >> 4, tx = t & 15;
    const int kbase = kc * 128;

    DECL_Q

    for (int k0 = 0; k0 < 128; k0 += 16) {
#pragma unroll
        for (int i = 0; i < 2; i++) {
            int idx = t + i * 256;
            int row = idx >> 2, kq = idx & 3;
            const float4 va = *reinterpret_cast<const float4*>(
                Ak + (size_t)row * Sn + kbase + k0 + kq * 4);
            As[kq * 4 + 0][row] = va.x;
            As[kq * 4 + 1][row] = va.y;
            As[kq * 4 + 2][row] = va.z;
            As[kq * 4 + 3][row] = va.w;
        }
#pragma unroll
        for (int i = 0; i < 2; i++) {
            int idx = t + i * 256;
            int row = idx >> 5, cq = idx & 31;
            *reinterpret_cast<float4*>(&Bs[row][cq * 4]) =
                *reinterpret_cast<const float4*>(V + (size_t)(kbase + k0 + row) * Dn + cq * 4);
        }
        __syncthreads();
#pragma unroll
        for (int kk = 0; kk < 16; kk++) {
            const float4 a0 = *reinterpret_cast<const float4*>(&As[kk][ty * 8]);
            const float4 a1 = *reinterpret_cast<const float4*>(&As[kk][ty * 8 + 4]);
            const unsigned long long rb0 =
                *reinterpret_cast<const unsigned long long*>(&Bs[kk][tx * 8 + 0]);
            const unsigned long long rb1 =
                *reinterpret_cast<const unsigned long long*>(&Bs[kk][tx * 8 + 2]);
            const unsigned long long rb2 =
                *reinterpret_cast<const unsigned long long*>(&Bs[kk][tx * 8 + 4]);
            const unsigned long long rb3 =
                *reinterpret_cast<const unsigned long long*>(&Bs[kk][tx * 8 + 6]);
            KSTEP8x8
        }
        __syncthreads();
    }

#define MP_STORE(I, i)                                                          \
    do {                                                                        \
        UNPACK_ROW(I)                                                           \
        float* dst = C + (size_t)(ty * 8 + (i)) * Dn + tx * 8;                  \
        *reinterpret_cast<float4*>(dst) = make_float4(c0, c1, c2, c3);          \
        *reinterpret_cast<float4*>(dst + 4) = make_float4(c4, c5, c6, c7);      \
    } while (0)
    MP_STORE(0, 0); MP_STORE(1, 1); MP_STORE(2, 2); MP_STORE(3, 3);
    MP_STORE(4, 4); MP_STORE(5, 5); MP_STORE(6, 6); MP_STORE(7, 7);
#undef MP_STORE
}

// ---------------------------------------------------------------------------
// Kernel 3: reduce split-K partials -> g_M
// ---------------------------------------------------------------------------
__global__ void reduceM_kernel() {
    int idx = blockIdx.x * blockDim.x + threadIdx.x;
    int b = idx >> 14;
    int r = idx & 16383;
    float s = 0.f;
#pragma unroll
    for (int p = 0; p < NCH; p++) s += g_Mpart[((size_t)(b * NCH + p)) * Dn * Dn + r];
    g_M[idx] = s;
}

// ---------------------------------------------------------------------------
// Kernel 4a: split-K gemmP partials. P_part[kc] = Wq[k-half]^T @ M[k-half]
// 32x128 h-tiles, K split in 2 halves of 64 -> grid (32, 2, Bn) = 256 CTAs.
// ---------------------------------------------------------------------------
__global__ __launch_bounds__(256) void gemmPpart_kernel(const float* __restrict__ Wq) {
    const int h0 = blockIdx.x * 32;
    const int kc = blockIdx.y;            // 0 or 1
    const int b = blockIdx.z;
    const float* Mb = g_M + (size_t)b * Dn * Dn;
    float* PP = g_Ppart + ((size_t)(kc * Bn + b)) * Hn * Dn;

    __shared__ __align__(16) float As[16][34];
    __shared__ __align__(16) float Bs[16][132];

    const int t = threadIdx.x;
    const int ty = t >> 4, tx = t & 15;
    const int kbase = kc * 64;

    float acc[2][8];
#pragma unroll
    for (int i = 0; i < 2; i++)
#pragma unroll
        for (int j = 0; j < 8; j++) acc[i][j] = 0.f;

    for (int k0 = 0; k0 < 64; k0 += 16) {
        {
            const int d = t >> 4, h = (t & 15) * 2;
            const float2 wv = *reinterpret_cast<const float2*>(
                Wq + (size_t)(kbase + k0 + d) * Hn + h0 + h);
            As[d][h] = wv.x;
            As[d][h + 1] = wv.y;
        }
#pragma unroll
        for (int i = 0; i < 2; i++) {
            int idx = t + i * 256;
            int row = idx >> 5, cq = idx & 31;
            *reinterpret_cast<float4*>(&Bs[row][cq * 4]) =
                *reinterpret_cast<const float4*>(
                    Mb + (size_t)(kbase + k0 + row) * Dn + cq * 4);
        }
        __syncthreads();
#pragma unroll
        for (int kk = 0; kk < 16; kk++) {
            const float ra0 = As[kk][ty];
            const float ra1 = As[kk][ty + 16];
            const float4 b0 = *reinterpret_cast<const float4*>(&Bs[kk][tx * 8]);
            const float4 b1 = *reinterpret_cast<const float4*>(&Bs[kk][tx * 8 + 4]);
            const float rb[8] = {b0.x, b0.y, b0.z, b0.w, b1.x, b1.y, b1.z, b1.w};
#pragma unroll
            for (int j = 0; j < 8; j++) acc[0][j] += ra0 * rb[j];
#pragma unroll
            for (int j = 0; j < 8; j++) acc[1][j] += ra1 * rb[j];
        }
        __syncthreads();
    }
#pragma unroll
    for (int i = 0; i < 2; i++) {
        float* dst = PP + (size_t)(h0 + ty + i * 16) * Dn + tx * 8;
        *reinterpret_cast<float4*>(dst) =
            make_float4(acc[i][0], acc[i][1], acc[i][2], acc[i][3]);
        *reinterpret_cast<float4*>(dst + 4) =
            make_float4(acc[i][4], acc[i][5], acc[i][6], acc[i][7]);
    }
}

// ---------------------------------------------------------------------------
// Kernel 4b: P = SCALE * (Ppart0 + Ppart1)
// ---------------------------------------------------------------------------
__global__ void reduceP_kernel() {
    const int i = blockIdx.x * blockDim.x + threadIdx.x;   // < Bn*Hn*Dn/4
    const float4 p0 = reinterpret_cast<const float4*>(g_Ppart)[i];
    const float4 p1 = reinterpret_cast<const float4*>(g_Ppart + (size_t)Bn * Hn * Dn)[i];
    reinterpret_cast<float4*>(g_P)[i] =
        make_float4((p0.x + p1.x) * SCALE, (p0.y + p1.y) * SCALE,
                    (p0.z + p1.z) * SCALE, (p0.w + p1.w) * SCALE);
}

// ---------------------------------------------------------------------------
// Kernel 5a/5b: suffix machinery (R10/R11 verbatim)
// ---------------------------------------------------------------------------
__global__ void chunksum_kernel() {
    const int c = blockIdx.x, b = blockIdx.y, e = threadIdx.x;
    const float* V = g_v + ((size_t)b * Sn + c * 128) * Dn;
    float s = 0.f;
#pragma unroll 8
    for (int i = 0; i < 128; i++) s += V[(size_t)i * Dn + e];
    g_chunk[((size_t)b * NCH + c) * Dn + e] = s;
}

__global__ void suffix_kernel() {
    const int c = blockIdx.x, b = blockIdx.y, e = threadIdx.x;
    float tail = 0.f;
    for (int cc = c + 1; cc < NCH; cc++) tail += g_chunk[((size_t)b * NCH + cc) * Dn + e];
    const float* V = g_v + ((size_t)b * Sn + c * 128) * Dn;
    float* Sx = g_sfx + ((size_t)b * Sn + c * 128) * Dn;
    for (int i = 127; i >= 0; i--) {
        Sx[(size_t)i * Dn + e] = tail;
        tail += V[(size_t)i * Dn + e];
    }
}

// ---------------------------------------------------------------------------
// Kernel 6: res = x @ P_b - 1e9 * sfx (R10/R11 verbatim)
// ---------------------------------------------------------------------------
__global__ __launch_bounds__(256) void final_kernel(const float* __restrict__ x,
                                                    float* __restrict__ out) {
    const int m0 = blockIdx.x * 128;
    const int b = m0 / Sn;
    const float* P = g_P + (size_t)b * Hn * Dn;

    __shared__ __align__(16) float As[16][132];
    __shared__ __align__(16) float Bs[16][132];

    const int t = threadIdx.x;
    const int ty = t >> 4, tx = t & 15;

    DECL_Q

    for (int k0 = 0; k0 < Hn; k0 += 16) {
#pragma unroll
        for (int i = 0; i < 2; i++) {
            int idx = t + i * 256;
            int row = idx >> 2, kq = idx & 3;
            const float4 va = *reinterpret_cast<const float4*>(
                x + (size_t)(m0 + row) * Hn + k0 + kq * 4);
            As[kq * 4 + 0][row] = va.x;
            As[kq * 4 + 1][row] = va.y;
            As[kq * 4 + 2][row] = va.z;
            As[kq * 4 + 3][row] = va.w;
        }
#pragma unroll
        for (int i = 0; i < 2; i++) {
            int idx = t + i * 256;
            int row = idx >> 5, cq = idx & 31;
            *reinterpret_cast<float4*>(&Bs[row][cq * 4]) =
                *reinterpret_cast<const float4*>(P + (size_t)(k0 + row) * Dn + cq * 4);
        }
        __syncthreads();
#pragma unroll
        for (int kk = 0; kk < 16; kk++) {
            const float4 a0 = *reinterpret_cast<const float4*>(&As[kk][ty * 8]);
            const float4 a1 = *reinterpret_cast<const float4*>(&As[kk][ty * 8 + 4]);
            const unsigned long long rb0 =
                *reinterpret_cast<const unsigned long long*>(&Bs[kk][tx * 8 + 0]);
            const unsigned long long rb1 =
                *reinterpret_cast<const unsigned long long*>(&Bs[kk][tx * 8 + 2]);
            const unsigned long long rb2 =
                *reinterpret_cast<const unsigned long long*>(&Bs[kk][tx * 8 + 4]);
            const unsigned long long rb3 =
                *reinterpret_cast<const unsigned long long*>(&Bs[kk][tx * 8 + 6]);
            KSTEP8x8
        }
        __syncthreads();
    }

#define FIN_STORE(I, i)                                                         \
    do {                                                                        \
        UNPACK_ROW(I)                                                           \
        const int m = m0 + ty * 8 + (i);                                        \
        const float* sp = g_sfx + (size_t)m * Dn + tx * 8;                      \
        const float4 s0 = *reinterpret_cast<const float4*>(sp);                 \
        const float4 s1 = *reinterpret_cast<const float4*>(sp + 4);             \
        float* dst = out + (size_t)m * Dn + tx * 8;                             \
        *reinterpret_cast<float4*>(dst) =                                       \
            make_float4(c0 - 1.0e9f * s0.x, c1 - 1.0e9f * s0.y,                 \
                        c2 - 1.0e9f * s0.z, c3 - 1.0e9f * s0.w);                \
        *reinterpret_cast<float4*>(dst + 4) =                                   \
            make_float4(c4 - 1.0e9f * s1.x, c5 - 1.0e9f * s1.y,                 \
                        c6 - 1.0e9f * s1.z, c7 - 1.0e9f * s1.w);                \
    } while (0)
    FIN_STORE(0, 0); FIN_STORE(1, 1); FIN_STORE(2, 2); FIN_STORE(3, 3);
    FIN_STORE(4, 4); FIN_STORE(5, 5); FIN_STORE(6, 6); FIN_STORE(7, 7);
#undef FIN_STORE
}

// ---------------------------------------------------------------------------
// launch
// ---------------------------------------------------------------------------
extern "C" void kernel_launch(void* const* d_in, const int* in_sizes, int n_in,
                              void* d_out, int out_size) {
    const float* x = (const float*)d_in[0];
    const float* Wq = (const float*)d_in[1];
    const float* Wk = (const float*)d_in[2];
    const float* Wv = (const float*)d_in[3];
    float* out = (float*)d_out;

    proj_kv_kernel<<<dim3(Bn * Sn / 128, 2), 256>>>(x, Wk, Wv);
    mpart_kernel<<<dim3(NCH, Bn), 256>>>();
    reduceM_kernel<<<256, 256>>>();
    gemmPpart_kernel<<<dim3(Hn / 32, 2, Bn), 256>>>(Wq);
    reduceP_kernel<<<Bn * Hn * Dn / 4 / 256, 256>>>();
    chunksum_kernel<<<dim3(NCH, Bn), 128>>>();
    suffix_kernel<<<dim3(NCH, Bn), 128>>>();
    final_kernel<<<Bn * Sn / 128, 256>>>(x, out);
}